// round 15
// baseline (speedup 1.0000x reference)
#include <cuda_runtime.h>
#include <cstdint>

#define Bb 32
#define Nn 1024
#define TDd 32
#define CINc 66
#define CSTR 80
#define EDd 10
#define OGg 128
#define OUu 64
#define COG (CINc*OGg)   // 8448
#define COU (CINc*OUu)   // 4224

typedef unsigned long long ull;

// ---------------- scratch ----------------
__device__ float g_ins [Bb*Nn*CSTR];
__device__ float g_p   [Bb*Nn*64];           // [nv1 | -nv2]
__device__ float g_q   [Bb*Nn*64];           // [nv2 |  nv1]
__device__ float g_ax  [Bb*Nn*CSTR];
__device__ float g_cand[Bb*Nn*CSTR];
__device__ float g_axc [Bb*Nn*CSTR];
__device__ float g_Wg0 [Nn*COG];
__device__ float g_Wg1 [Nn*COG];
__device__ float g_Wu0 [Nn*COU];
__device__ float g_Wu1 [Nn*COU];
__device__ float g_r   [Bb*Nn*OUu];

__device__ __forceinline__ float sigm(float v){ return 1.f/(1.f+__expf(-v)); }

// ---- tf32 mma.sync helpers (base-PTX only) ----
__device__ __forceinline__ uint32_t tf32u(float v){
    uint32_t o; asm("cvt.rna.tf32.f32 %0, %1;" : "=r"(o) : "f"(v)); return o;
}
__device__ __forceinline__ void mma8(float* c, const uint32_t* a, const uint32_t* b){
    asm volatile("mma.sync.aligned.m16n8k8.row.col.f32.tf32.tf32.f32 "
        "{%0,%1,%2,%3}, {%4,%5,%6,%7}, {%8,%9}, {%0,%1,%2,%3};"
        : "+f"(c[0]), "+f"(c[1]), "+f"(c[2]), "+f"(c[3])
        : "r"(a[0]), "r"(a[1]), "r"(a[2]), "r"(a[3]), "r"(b[0]), "r"(b[1]));
}

// ---------------- K1: build ins (col79=1), tiny MLPs -> p,q ----
__global__ __launch_bounds__(128) void k_prep(
    const float* __restrict__ x, const float* __restrict__ st,
    const float* __restrict__ ne0, const float* __restrict__ ne1,
    const float* __restrict__ w11, const float* __restrict__ b11,
    const float* __restrict__ w12, const float* __restrict__ b12,
    const float* __restrict__ w13, const float* __restrict__ b13,
    const float* __restrict__ w21, const float* __restrict__ b21,
    const float* __restrict__ w22, const float* __restrict__ b22,
    const float* __restrict__ w23, const float* __restrict__ b23)
{
    __shared__ float sw11[1056], sw21[1056];
    __shared__ float sb11[16], sb21[16];
    __shared__ float sw12[32], sw22[32], sb12[2], sb22[2];
    __shared__ float sw13[64], sw23[64], sb13[32], sb23[32];
    __shared__ float sv[128*67];

    int t = threadIdx.x;
    for (int i = t; i < 1056; i += 128){ sw11[i] = w11[i]; sw21[i] = w21[i]; }
    if (t < 16){ sb11[t] = b11[t]; sb21[t] = b21[t]; }
    if (t < 32){
        sw12[t] = w12[t]; sw22[t] = w22[t];
        sw13[t] = w13[t]; sw23[t] = w23[t];
        sw13[32+t] = w13[32+t]; sw23[32+t] = w23[32+t];
        sb13[t] = b13[t]; sb23[t] = b23[t];
    }
    if (t < 2){ sb12[t] = b12[t]; sb22[t] = b22[t]; }

    int idx0 = blockIdx.x*128;
    for (int e = t; e < 256; e += 128){
        int r = e >> 1, c = e & 1;
        float v = x[idx0*2 + e];
        sv[r*67 + c] = v;
        g_ins[(size_t)(idx0+r)*CSTR + c] = v;
    }
    for (int e = t; e < 128*64; e += 128){
        int r = e >> 6, c = e & 63;
        float v = st[(size_t)idx0*64 + e];
        sv[r*67 + 2 + c] = v;
        g_ins[(size_t)(idx0+r)*CSTR + 2 + c] = v;
    }
    for (int e = t; e < 128*14; e += 128){
        int r = e/14, c = 66 + e%14;
        g_ins[(size_t)(idx0+r)*CSTR + c] = (c == 79) ? 1.f : 0.f;
    }
    __syncthreads();

    int idx = idx0 + t;
    int b = idx >> 10;
    const float* vrow = &sv[t*67];

    {
        float h1[16];
        #pragma unroll
        for (int j = 0; j < 16; j++){
            float a = sb11[j];
            for (int i = 0; i < 66; i++) a += vrow[i]*sw11[i*16+j];
            h1[j] = sigm(a);
        }
        float a0 = sb12[0], a1 = sb12[1];
        #pragma unroll
        for (int j = 0; j < 16; j++){ a0 += h1[j]*sw12[j*2]; a1 += h1[j]*sw12[j*2+1]; }
        float h2a = sigm(a0), h2b = sigm(a1);
        #pragma unroll
        for (int o = 0; o < 32; o++){
            float f = sb13[o] + h2a*sw13[o] + h2b*sw13[32+o];
            float nv = tanhf(ne0[b*TDd + o]*f);
            g_p[(size_t)idx*64 + o] = nv;
            g_q[(size_t)idx*64 + 32 + o] = nv;
        }
    }
    {
        float h1[16];
        #pragma unroll
        for (int j = 0; j < 16; j++){
            float a = sb21[j];
            for (int i = 0; i < 66; i++) a += vrow[i]*sw21[i*16+j];
            h1[j] = sigm(a);
        }
        float a0 = sb22[0], a1 = sb22[1];
        #pragma unroll
        for (int j = 0; j < 16; j++){ a0 += h1[j]*sw22[j*2]; a1 += h1[j]*sw22[j*2+1]; }
        float h2a = sigm(a0), h2b = sigm(a1);
        #pragma unroll
        for (int o = 0; o < 32; o++){
            float f = sb23[o] + h2a*sw23[o] + h2b*sw23[32+o];
            float nv = tanhf(ne1[b*TDd + o]*f);
            g_p[(size_t)idx*64 + 32 + o] = -nv;
            g_q[(size_t)idx*64 + o] = nv;
        }
    }
}

// ---------------- K2: effective per-node weights ----------------
template<int CO, bool GATE>
__global__ __launch_bounds__(128) void k_wmix(const float* __restrict__ pool,
                                              const float* __restrict__ ne2)
{
    __shared__ float sne[64*EDd];
    int t = threadIdx.x;
    int row0 = blockIdx.y*64;
    for (int i = t; i < 64*EDd; i += 128) sne[i] = ne2[row0*EDd + i];
    __syncthreads();

    int col = blockIdx.x*128 + t;
    float ga[EDd], gb[EDd];
    #pragma unroll
    for (int d = 0; d < EDd; d++){
        ga[d] = pool[(size_t)(d*4+0)*CO + col] + pool[(size_t)(d*4+2)*CO + col];
        gb[d] = pool[(size_t)(d*4+1)*CO + col] + pool[(size_t)(d*4+3)*CO + col];
    }
    float* o0 = GATE ? g_Wg0 : g_Wu0;
    float* o1 = GATE ? g_Wg1 : g_Wu1;
    for (int r = 0; r < 64; r++){
        float a0 = 0.f, a1 = 0.f;
        #pragma unroll
        for (int d = 0; d < EDd; d++){ float e = sne[r*EDd+d]; a0 += e*ga[d]; a1 += e*gb[d]; }
        o0[(size_t)(row0+r)*CO + col] = a0;
        o1[(size_t)(row0+r)*CO + col] = a1;
    }
}

// ---------------- K3: FUSED  Y = (relu(P·Q^T) @ X + X)/rowsum ----------------
// 128-thread CTAs (4 warps), row tile 64, grid (16, Bb) = 512 CTAs -> 3 CTAs/SM.
// Double-buffered sQ/sX, LDG prefetch under adj-mma, 2 syncs/chunk.
// smem words: sP[64][68]=4352 @0 | sQ[2][32][68]=4352 @4352 | sX[2][80][44]=7040 @8704
//             sAdj[64][36]=2304 @15744 | srs[64] @18048  -> 18112 w = 72448 B
#define FUSED_SMEM (18112*4)
template<bool SECOND>
__global__ __launch_bounds__(128, 3) void k_fused(){
    extern __shared__ uint32_t fsm[];
    uint32_t* sP   = fsm;                      // [64][68]
    uint32_t* sQb  = fsm + 4352;               // [2][32*68]
    uint32_t* sXb  = fsm + 8704;               // [2][80*44]
    uint32_t* sAdj = fsm + 15744;              // [64][36]
    float*    srs  = (float*)(fsm + 18048);
    const float* X = SECOND ? g_cand : g_ins;
    float*       Y = SECOND ? g_axc  : g_ax;
    int t = threadIdx.x, w = t >> 5, lane = t & 31;
    int wg = w >> 1, cg = w & 1;
    int quad = lane >> 2, tig = lane & 3;
    int b = blockIdx.y;
    int row0 = blockIdx.x*64;
    const float* Pb = g_p + (size_t)b*Nn*64;
    const float* Qb = g_q + (size_t)b*Nn*64;
    const float* Xb = X + (size_t)b*Nn*CSTR;

    // stage P rows once (tf32), stride 68
    #pragma unroll
    for (int p = 0; p < 8; p++){
        int e = t + p*128;                     // 1024 float4 = 64x64
        int r = e >> 4, m = e & 15;
        float4 v = *(const float4*)&Pb[(size_t)(row0+r)*64 + m*4];
        uint4 u;
        u.x = tf32u(v.x); u.y = tf32u(v.y); u.z = tf32u(v.z); u.w = tf32u(v.w);
        *(uint4*)&sP[r*68 + m*4] = u;
    }
    // stage chunk 0 of Q and X directly
    {
        uint32_t* sQ = sQb;
        uint32_t* sX = sXb;
        #pragma unroll
        for (int p = 0; p < 4; p++){
            int e = t + p*128;                 // 512 float4 = 32x64
            int c = e >> 4, m = e & 15;
            float4 v = *(const float4*)&Qb[(size_t)c*64 + m*4];
            uint4 u;
            u.x = tf32u(v.x); u.y = tf32u(v.y); u.z = tf32u(v.z); u.w = tf32u(v.w);
            *(uint4*)&sQ[c*68 + m*4] = u;
        }
        #pragma unroll
        for (int p = 0; p < 20; p++){
            int e = t + p*128;                 // 2560
            int k = e/80, n = e%80;
            sX[n*44 + k] = tf32u(Xb[(size_t)k*CSTR + n]);
        }
    }
    __syncthreads();

    float accY[2][5][4] = {};

    for (int kc = 0; kc < 32; kc++){
        int cur = kc & 1;
        uint32_t* sQ = sQb + cur*(32*68);
        uint32_t* sX = sXb + cur*(80*44);
        uint32_t* nQ = sQb + (cur^1)*(32*68);
        uint32_t* nX = sXb + (cur^1)*(80*44);

        // prefetch next chunk into registers (LDG issued now, consumed after adj)
        float4 pq[4];
        float  px[20];
        if (kc < 31){
            #pragma unroll
            for (int p = 0; p < 4; p++){
                int e = t + p*128;
                int c = e >> 4, m = e & 15;
                pq[p] = *(const float4*)&Qb[(size_t)((kc+1)*32 + c)*64 + m*4];
            }
            #pragma unroll
            for (int p = 0; p < 20; p++){
                int e = t + p*128;
                int k = e/80, n = e%80;
                px[p] = Xb[(size_t)((kc+1)*32 + k)*CSTR + n];
            }
        }

        // adj mma: warp w = m16 tile w (rows w*16..+16), 4 n8 tiles, K=64
        float accA[4][4] = {};
        #pragma unroll
        for (int k8 = 0; k8 < 8; k8++){
            int kk = k8*8;
            uint32_t a[4];
            int R = w*16 + quad;
            a[0] = sP[(R  )*68 + kk + tig];
            a[1] = sP[(R+8)*68 + kk + tig];
            a[2] = sP[(R  )*68 + kk + tig + 4];
            a[3] = sP[(R+8)*68 + kk + tig + 4];
            #pragma unroll
            for (int nj = 0; nj < 4; nj++){
                int n = nj*8 + quad;
                uint32_t bq[2];
                bq[0] = sQ[n*68 + kk + tig];
                bq[1] = sQ[n*68 + kk + tig + 4];
                mma8(accA[nj], a, bq);
            }
        }
        // relu + tf32 + STS to sAdj [row][k] stride 36
        {
            int R = w*16 + quad;
            #pragma unroll
            for (int nj = 0; nj < 4; nj++){
                uint2 u0, u1;
                u0.x = tf32u(fmaxf(accA[nj][0], 0.f));
                u0.y = tf32u(fmaxf(accA[nj][1], 0.f));
                u1.x = tf32u(fmaxf(accA[nj][2], 0.f));
                u1.y = tf32u(fmaxf(accA[nj][3], 0.f));
                *(uint2*)&sAdj[(R  )*36 + nj*8 + 2*tig] = u0;
                *(uint2*)&sAdj[(R+8)*36 + nj*8 + 2*tig] = u1;
            }
        }
        // store prefetched next chunk (LDG data has arrived under adj-mma)
        if (kc < 31){
            #pragma unroll
            for (int p = 0; p < 4; p++){
                int e = t + p*128;
                int c = e >> 4, m = e & 15;
                uint4 u;
                u.x = tf32u(pq[p].x); u.y = tf32u(pq[p].y);
                u.z = tf32u(pq[p].z); u.w = tf32u(pq[p].w);
                *(uint4*)&nQ[c*68 + m*4] = u;
            }
            #pragma unroll
            for (int p = 0; p < 20; p++){
                int e = t + p*128;
                int k = e/80, n = e%80;
                nX[n*44 + k] = tf32u(px[p]);
            }
        }
        __syncthreads();   // sAdj ready + next buffers staged

        // spmm mma: accY += adjc @ Xc   (warp (wg,cg): rows wg*32..+32, cols cg*40)
        #pragma unroll
        for (int k8 = 0; k8 < 4; k8++){
            int kk = k8*8;
            uint32_t a[2][4];
            #pragma unroll
            for (int mi = 0; mi < 2; mi++){
                int R = wg*32 + mi*16 + quad;
                a[mi][0] = sAdj[(R  )*36 + kk + tig];
                a[mi][1] = sAdj[(R+8)*36 + kk + tig];
                a[mi][2] = sAdj[(R  )*36 + kk + tig + 4];
                a[mi][3] = sAdj[(R+8)*36 + kk + tig + 4];
            }
            #pragma unroll
            for (int nj = 0; nj < 5; nj++){
                int n = cg*40 + nj*8 + quad;
                uint32_t bf[2];
                bf[0] = sX[n*44 + kk + tig];
                bf[1] = sX[n*44 + kk + tig + 4];
                mma8(accY[0][nj], a[0], bf);
                mma8(accY[1][nj], a[1], bf);
            }
        }
        __syncthreads();   // all warps done with sAdj (+cur buffers) before next adj overwrites
    }

    // rowsum from ones-col 79: cg==1, nj==4, tig==3 -> c1/c3 = col 79
    if (cg == 1 && tig == 3){
        #pragma unroll
        for (int mi = 0; mi < 2; mi++){
            srs[wg*32 + mi*16 + quad    ] = accY[mi][4][1] + 1.f;
            srs[wg*32 + mi*16 + quad + 8] = accY[mi][4][3] + 1.f;
        }
    }
    __syncthreads();

    #pragma unroll
    for (int mi = 0; mi < 2; mi++){
        #pragma unroll
        for (int rp = 0; rp < 2; rp++){
            int lr  = wg*32 + mi*16 + quad + rp*8;
            int row = row0 + lr;
            float inv = 1.f/srs[lr];
            const float* xr = Xb + (size_t)row*CSTR;
            float* yr = Y + ((size_t)b*Nn + row)*CSTR;
            #pragma unroll
            for (int nj = 0; nj < 5; nj++){
                int col = cg*40 + nj*8 + 2*tig;
                float2 xv = *(const float2*)&xr[col];
                float2 o;
                o.x = (accY[mi][nj][rp*2+0] + xv.x)*inv;
                o.y = (accY[mi][nj][rp*2+1] + xv.y)*inv;
                *(float2*)&yr[col] = o;
            }
        }
    }
}

// ---------------- K5: gate node-GEMM -> z,r; builds cand (col79=1); inline bias ----
__global__ __launch_bounds__(128) void k_gate(const float* __restrict__ x,
                                              const float* __restrict__ state,
                                              const float* __restrict__ bg_pool,
                                              const float* __restrict__ ne2)
{
    extern __shared__ float sm[];
    float* sW0 = sm;
    float* sW1 = sm + COG;
    float* sX  = sm + 2*COG;
    float* sAX = sm + 2*COG + 2112;
    int n = blockIdx.x, t = threadIdx.x;
    int bg = t >> 5, og = t & 31;

    {
        float4* d0 = (float4*)sW0; const float4* s0 = (const float4*)(g_Wg0 + (size_t)n*COG);
        float4* d1 = (float4*)sW1; const float4* s1 = (const float4*)(g_Wg1 + (size_t)n*COG);
        for (int e = t; e < COG/4; e += 128){ d0[e] = s0[e]; d1[e] = s1[e]; }
    }
    for (int e = t; e < 32*66; e += 128){
        int bi = e/66, i = e%66;
        sX [e] = g_ins[((size_t)bi*Nn + n)*CSTR + i];
        sAX[e] = g_ax [((size_t)bi*Nn + n)*CSTR + i];
    }
    float4 bias = make_float4(0.f, 0.f, 0.f, 0.f);
    {
        #pragma unroll
        for (int d = 0; d < EDd; d++){
            float e = ne2[n*EDd + d];
            float4 bp = *(const float4*)&bg_pool[d*OGg + og*4];
            bias.x += e*bp.x; bias.y += e*bp.y; bias.z += e*bp.z; bias.w += e*bp.w;
        }
    }
    __syncthreads();

    float4 acc[8] = {};
    #pragma unroll 2
    for (int i = 0; i < 66; i++){
        float4 w0 = ((const float4*)sW0)[i*32 + og];
        float4 w1 = ((const float4*)sW1)[i*32 + og];
        #pragma unroll
        for (int bb = 0; bb < 8; bb++){
            int bi = bg*8 + bb;
            float xv = sX[bi*66 + i], av = sAX[bi*66 + i];
            acc[bb].x += xv*w0.x + av*w1.x;
            acc[bb].y += xv*w0.y + av*w1.y;
            acc[bb].z += xv*w0.z + av*w1.z;
            acc[bb].w += xv*w0.w + av*w1.w;
        }
    }
    int o0 = og*4;
    #pragma unroll
    for (int bb = 0; bb < 8; bb++){
        int bi = bg*8 + bb;
        size_t bn = (size_t)bi*Nn + n;
        float vals[4] = { acc[bb].x + bias.x, acc[bb].y + bias.y,
                          acc[bb].z + bias.z, acc[bb].w + bias.w };
        #pragma unroll
        for (int c = 0; c < 4; c++){
            float zz = sigm(vals[c]);
            int o = o0 + c;
            if (o < 64) g_cand[bn*CSTR + 2 + o] = zz * state[bn*64 + o];
            else        g_r  [bn*64 + (o - 64)] = zz;
        }
    }
    if (og == 0){
        #pragma unroll
        for (int bb = 0; bb < 8; bb++){
            size_t bn = (size_t)(bg*8 + bb)*Nn + n;
            g_cand[bn*CSTR + 0] = x[bn*2 + 0];
            g_cand[bn*CSTR + 1] = x[bn*2 + 1];
            #pragma unroll
            for (int c = 66; c < 80; c++) g_cand[bn*CSTR + c] = (c == 79) ? 1.f : 0.f;
        }
    }
}

// ---------------- K8: upd node-GEMM -> hc; final out; inline bias ----------------
__global__ __launch_bounds__(128) void k_upd(const float* __restrict__ state,
                                             float* __restrict__ out,
                                             const float* __restrict__ bu_pool,
                                             const float* __restrict__ ne2)
{
    extern __shared__ float sm[];
    float* sW0 = sm;
    float* sW1 = sm + COU;
    float* sX  = sm + 2*COU;
    float* sAX = sm + 2*COU + 2112;
    int n = blockIdx.x, t = threadIdx.x;
    int bg = t >> 5, og = t & 31;

    {
        float4* d0 = (float4*)sW0; const float4* s0 = (const float4*)(g_Wu0 + (size_t)n*COU);
        float4* d1 = (float4*)sW1; const float4* s1 = (const float4*)(g_Wu1 + (size_t)n*COU);
        for (int e = t; e < COU/4; e += 128){ d0[e] = s0[e]; d1[e] = s1[e]; }
    }
    for (int e = t; e < 32*66; e += 128){
        int bi = e/66, i = e%66;
        sX [e] = g_cand[((size_t)bi*Nn + n)*CSTR + i];
        sAX[e] = g_axc [((size_t)bi*Nn + n)*CSTR + i];
    }
    float2 bias = make_float2(0.f, 0.f);
    {
        #pragma unroll
        for (int d = 0; d < EDd; d++){
            float e = ne2[n*EDd + d];
            float2 bp = *(const float2*)&bu_pool[d*OUu + og*2];
            bias.x += e*bp.x; bias.y += e*bp.y;
        }
    }
    __syncthreads();

    float2 acc[8] = {};
    #pragma unroll 2
    for (int i = 0; i < 66; i++){
        float2 w0 = ((const float2*)sW0)[i*32 + og];
        float2 w1 = ((const float2*)sW1)[i*32 + og];
        #pragma unroll
        for (int bb = 0; bb < 8; bb++){
            int bi = bg*8 + bb;
            float xv = sX[bi*66 + i], av = sAX[bi*66 + i];
            acc[bb].x += xv*w0.x + av*w1.x;
            acc[bb].y += xv*w0.y + av*w1.y;
        }
    }
    #pragma unroll
    for (int bb = 0; bb < 8; bb++){
        int bi = bg*8 + bb;
        size_t bn = (size_t)bi*Nn + n;
        #pragma unroll
        for (int c = 0; c < 2; c++){
            int o = og*2 + c;
            float hc = tanhf((c ? acc[bb].y + bias.y : acc[bb].x + bias.x));
            float rr = g_r[bn*64 + o];
            float sv = state[bn*64 + o];
            out[bn*64 + o] = rr*sv + (1.f - rr)*hc;
        }
    }
}

// ---------------- launcher ----------------
extern "C" void kernel_launch(void* const* d_in, const int* in_sizes, int n_in,
                              void* d_out, int out_size)
{
    const float* x      = (const float*)d_in[0];
    const float* state  = (const float*)d_in[1];
    const float* ne0    = (const float*)d_in[2];
    const float* ne1    = (const float*)d_in[3];
    const float* ne2    = (const float*)d_in[4];
    const float* f1w1   = (const float*)d_in[5];
    const float* f1b1   = (const float*)d_in[6];
    const float* f1w2   = (const float*)d_in[7];
    const float* f1b2   = (const float*)d_in[8];
    const float* f1w3   = (const float*)d_in[9];
    const float* f1b3   = (const float*)d_in[10];
    const float* f2w1   = (const float*)d_in[11];
    const float* f2b1   = (const float*)d_in[12];
    const float* f2w2   = (const float*)d_in[13];
    const float* f2b2   = (const float*)d_in[14];
    const float* f2w3   = (const float*)d_in[15];
    const float* f2b3   = (const float*)d_in[16];
    const float* gate_w = (const float*)d_in[17];
    const float* gate_b = (const float*)d_in[18];
    const float* upd_w  = (const float*)d_in[19];
    const float* upd_b  = (const float*)d_in[20];
    float* out = (float*)d_out;

    cudaFuncSetAttribute(k_fused<false>, cudaFuncAttributeMaxDynamicSharedMemorySize, FUSED_SMEM);
    cudaFuncSetAttribute(k_fused<true>,  cudaFuncAttributeMaxDynamicSharedMemorySize, FUSED_SMEM);
    cudaFuncSetAttribute(k_gate, cudaFuncAttributeMaxDynamicSharedMemorySize, (2*COG + 2*2112)*4);
    cudaFuncSetAttribute(k_upd,  cudaFuncAttributeMaxDynamicSharedMemorySize, (2*COU + 2*2112)*4);

    // Launch #4 (the one ncu captures) = k_fused<false>.
    k_prep<<<256, 128>>>(x, state, ne0, ne1,
                         f1w1, f1b1, f1w2, f1b2, f1w3, f1b3,
                         f2w1, f2b1, f2w2, f2b2, f2w3, f2b3);
    k_wmix<COG, true ><<<dim3(COG/128, Nn/64), 128>>>(gate_w, ne2);
    k_wmix<COU, false><<<dim3(COU/128, Nn/64), 128>>>(upd_w,  ne2);
    k_fused<false><<<dim3(16, Bb), 128, FUSED_SMEM>>>();
    k_gate<<<Nn, 128, (2*COG + 2*2112)*4>>>(x, state, gate_b, ne2);
    k_fused<true><<<dim3(16, Bb), 128, FUSED_SMEM>>>();
    k_upd<<<Nn, 128, (2*COU + 2*2112)*4>>>(state, out, upd_b, ne2);
}

// round 16
// speedup vs baseline: 1.1117x; 1.1117x over previous
#include <cuda_runtime.h>
#include <cstdint>

#define Bb 32
#define Nn 1024
#define TDd 32
#define CINc 66
#define CSTR 80
#define EDd 10
#define OGg 128
#define OUu 64
#define COG (CINc*OGg)   // 8448
#define COU (CINc*OUu)   // 4224

typedef unsigned long long ull;

// ---------------- scratch ----------------
__device__ float g_ins [Bb*Nn*CSTR];
__device__ float g_p   [Bb*Nn*64];           // [nv1 | -nv2]
__device__ float g_q   [Bb*Nn*64];           // [nv2 |  nv1]
__device__ float g_ax  [Bb*Nn*CSTR];
__device__ float g_cand[Bb*Nn*CSTR];
__device__ float g_axc [Bb*Nn*CSTR];
__device__ float g_Wg0 [Nn*COG];
__device__ float g_Wg1 [Nn*COG];
__device__ float g_Wu0 [Nn*COU];
__device__ float g_Wu1 [Nn*COU];
__device__ float g_r   [Bb*Nn*OUu];

__device__ __forceinline__ float sigm(float v){ return 1.f/(1.f+__expf(-v)); }

// ---- tf32 mma.sync helpers (base-PTX only) ----
__device__ __forceinline__ uint32_t tf32u(float v){
    uint32_t o; asm("cvt.rna.tf32.f32 %0, %1;" : "=r"(o) : "f"(v)); return o;
}
__device__ __forceinline__ void mma8(float* c, const uint32_t* a, const uint32_t* b){
    asm volatile("mma.sync.aligned.m16n8k8.row.col.f32.tf32.tf32.f32 "
        "{%0,%1,%2,%3}, {%4,%5,%6,%7}, {%8,%9}, {%0,%1,%2,%3};"
        : "+f"(c[0]), "+f"(c[1]), "+f"(c[2]), "+f"(c[3])
        : "r"(a[0]), "r"(a[1]), "r"(a[2]), "r"(a[3]), "r"(b[0]), "r"(b[1]));
}

// C-fragment (16x8, relu'd tf32 uints) -> A-fragment (m16k8) via warp shuffles.
// C layout: thread(q,t) holds (q,2t),(q,2t+1),(q+8,2t),(q+8,2t+1).
// A layout: thread(q,t) needs (q,t),(q+8,t),(q,t+4),(q+8,t+4).
__device__ __forceinline__ void cfrag_to_afrag(const uint32_t cu[4], uint32_t aT[4],
                                               int quad, int tig){
    const unsigned full = 0xffffffffu;
    int s0 = quad*4 + (tig>>1);
    int s1 = s0 + 2;
    uint32_t x0 = __shfl_sync(full, cu[0], s0);
    uint32_t x1 = __shfl_sync(full, cu[1], s0);
    uint32_t x2 = __shfl_sync(full, cu[2], s0);
    uint32_t x3 = __shfl_sync(full, cu[3], s0);
    uint32_t y0 = __shfl_sync(full, cu[0], s1);
    uint32_t y1 = __shfl_sync(full, cu[1], s1);
    uint32_t y2 = __shfl_sync(full, cu[2], s1);
    uint32_t y3 = __shfl_sync(full, cu[3], s1);
    bool odd = (tig & 1) != 0;
    aT[0] = odd ? x1 : x0;
    aT[1] = odd ? x3 : x2;
    aT[2] = odd ? y1 : y0;
    aT[3] = odd ? y3 : y2;
}

// ---------------- K1: build ins (col79=1), tiny MLPs -> p,q ----
__global__ __launch_bounds__(128) void k_prep(
    const float* __restrict__ x, const float* __restrict__ st,
    const float* __restrict__ ne0, const float* __restrict__ ne1,
    const float* __restrict__ w11, const float* __restrict__ b11,
    const float* __restrict__ w12, const float* __restrict__ b12,
    const float* __restrict__ w13, const float* __restrict__ b13,
    const float* __restrict__ w21, const float* __restrict__ b21,
    const float* __restrict__ w22, const float* __restrict__ b22,
    const float* __restrict__ w23, const float* __restrict__ b23)
{
    __shared__ float sw11[1056], sw21[1056];
    __shared__ float sb11[16], sb21[16];
    __shared__ float sw12[32], sw22[32], sb12[2], sb22[2];
    __shared__ float sw13[64], sw23[64], sb13[32], sb23[32];
    __shared__ float sv[128*67];

    int t = threadIdx.x;
    for (int i = t; i < 1056; i += 128){ sw11[i] = w11[i]; sw21[i] = w21[i]; }
    if (t < 16){ sb11[t] = b11[t]; sb21[t] = b21[t]; }
    if (t < 32){
        sw12[t] = w12[t]; sw22[t] = w22[t];
        sw13[t] = w13[t]; sw23[t] = w23[t];
        sw13[32+t] = w13[32+t]; sw23[32+t] = w23[32+t];
        sb13[t] = b13[t]; sb23[t] = b23[t];
    }
    if (t < 2){ sb12[t] = b12[t]; sb22[t] = b22[t]; }

    int idx0 = blockIdx.x*128;
    for (int e = t; e < 256; e += 128){
        int r = e >> 1, c = e & 1;
        float v = x[idx0*2 + e];
        sv[r*67 + c] = v;
        g_ins[(size_t)(idx0+r)*CSTR + c] = v;
    }
    for (int e = t; e < 128*64; e += 128){
        int r = e >> 6, c = e & 63;
        float v = st[(size_t)idx0*64 + e];
        sv[r*67 + 2 + c] = v;
        g_ins[(size_t)(idx0+r)*CSTR + 2 + c] = v;
    }
    for (int e = t; e < 128*14; e += 128){
        int r = e/14, c = 66 + e%14;
        g_ins[(size_t)(idx0+r)*CSTR + c] = (c == 79) ? 1.f : 0.f;
    }
    __syncthreads();

    int idx = idx0 + t;
    int b = idx >> 10;
    const float* vrow = &sv[t*67];

    {
        float h1[16];
        #pragma unroll
        for (int j = 0; j < 16; j++){
            float a = sb11[j];
            for (int i = 0; i < 66; i++) a += vrow[i]*sw11[i*16+j];
            h1[j] = sigm(a);
        }
        float a0 = sb12[0], a1 = sb12[1];
        #pragma unroll
        for (int j = 0; j < 16; j++){ a0 += h1[j]*sw12[j*2]; a1 += h1[j]*sw12[j*2+1]; }
        float h2a = sigm(a0), h2b = sigm(a1);
        #pragma unroll
        for (int o = 0; o < 32; o++){
            float f = sb13[o] + h2a*sw13[o] + h2b*sw13[32+o];
            float nv = tanhf(ne0[b*TDd + o]*f);
            g_p[(size_t)idx*64 + o] = nv;
            g_q[(size_t)idx*64 + 32 + o] = nv;
        }
    }
    {
        float h1[16];
        #pragma unroll
        for (int j = 0; j < 16; j++){
            float a = sb21[j];
            for (int i = 0; i < 66; i++) a += vrow[i]*sw21[i*16+j];
            h1[j] = sigm(a);
        }
        float a0 = sb22[0], a1 = sb22[1];
        #pragma unroll
        for (int j = 0; j < 16; j++){ a0 += h1[j]*sw22[j*2]; a1 += h1[j]*sw22[j*2+1]; }
        float h2a = sigm(a0), h2b = sigm(a1);
        #pragma unroll
        for (int o = 0; o < 32; o++){
            float f = sb23[o] + h2a*sw23[o] + h2b*sw23[32+o];
            float nv = tanhf(ne1[b*TDd + o]*f);
            g_p[(size_t)idx*64 + 32 + o] = -nv;
            g_q[(size_t)idx*64 + o] = nv;
        }
    }
}

// ---------------- K2: effective per-node weights ----------------
template<int CO, bool GATE>
__global__ __launch_bounds__(128) void k_wmix(const float* __restrict__ pool,
                                              const float* __restrict__ ne2)
{
    __shared__ float sne[64*EDd];
    int t = threadIdx.x;
    int row0 = blockIdx.y*64;
    for (int i = t; i < 64*EDd; i += 128) sne[i] = ne2[row0*EDd + i];
    __syncthreads();

    int col = blockIdx.x*128 + t;
    float ga[EDd], gb[EDd];
    #pragma unroll
    for (int d = 0; d < EDd; d++){
        ga[d] = pool[(size_t)(d*4+0)*CO + col] + pool[(size_t)(d*4+2)*CO + col];
        gb[d] = pool[(size_t)(d*4+1)*CO + col] + pool[(size_t)(d*4+3)*CO + col];
    }
    float* o0 = GATE ? g_Wg0 : g_Wu0;
    float* o1 = GATE ? g_Wg1 : g_Wu1;
    for (int r = 0; r < 64; r++){
        float a0 = 0.f, a1 = 0.f;
        #pragma unroll
        for (int d = 0; d < EDd; d++){ float e = sne[r*EDd+d]; a0 += e*ga[d]; a1 += e*gb[d]; }
        o0[(size_t)(row0+r)*CO + col] = a0;
        o1[(size_t)(row0+r)*CO + col] = a1;
    }
}

// ---------------- K3: FUSED  Y = (relu(P·Q^T) @ X + X)/rowsum ----------------
// 256 thr (8 warps), 128-row tile, grid (8, Bb) = 256 CTAs, 2 CTAs/SM.
// Warp w owns rows w*16..+16 END-TO-END: adj-mma (4 n8 = chunk's 32 k), relu+tf32 in
// regs, shfl fragment-transpose, spmm-mma. No sAdj smem; ONE sync per chunk
// (double-buffered sQ/sX with register prefetch). Rowsum via warp shfl (ones-col 79).
// smem words: sP[128][68]=8704 @0 | sQ[2][32*68]=4352 @8704 | sX[2][80*44]=7040 @13056
//             total 20096 w = 80384 B
#define FUSED_SMEM (20096*4)
template<bool SECOND>
__global__ __launch_bounds__(256, 2) void k_fused(){
    extern __shared__ uint32_t fsm[];
    uint32_t* sP  = fsm;                       // [128][68]
    uint32_t* sQb = fsm + 8704;                // [2][32*68]
    uint32_t* sXb = fsm + 13056;               // [2][80*44] (n-major, stride 44)
    const float* X = SECOND ? g_cand : g_ins;
    float*       Y = SECOND ? g_axc  : g_ax;
    int t = threadIdx.x, w = t >> 5, lane = t & 31;
    int quad = lane >> 2, tig = lane & 3;
    int b = blockIdx.y;
    int row0 = blockIdx.x*128;
    const float* Pb = g_p + (size_t)b*Nn*64;
    const float* Qb = g_q + (size_t)b*Nn*64;
    const float* Xb = X + (size_t)b*Nn*CSTR;

    // stage P rows once (tf32), stride 68
    #pragma unroll
    for (int p = 0; p < 8; p++){
        int e = t + p*256;                     // 2048 float4 = 128x64
        int r = e >> 4, m = e & 15;
        float4 v = *(const float4*)&Pb[(size_t)(row0+r)*64 + m*4];
        uint4 u;
        u.x = tf32u(v.x); u.y = tf32u(v.y); u.z = tf32u(v.z); u.w = tf32u(v.w);
        *(uint4*)&sP[r*68 + m*4] = u;
    }
    // stage chunk 0
    {
        #pragma unroll
        for (int p = 0; p < 2; p++){
            int e = t + p*256;                 // 512 float4 = 32x64
            int c = e >> 4, m = e & 15;
            float4 v = *(const float4*)&Qb[(size_t)c*64 + m*4];
            uint4 u;
            u.x = tf32u(v.x); u.y = tf32u(v.y); u.z = tf32u(v.z); u.w = tf32u(v.w);
            *(uint4*)&sQb[c*68 + m*4] = u;
        }
        #pragma unroll
        for (int p = 0; p < 10; p++){
            int e = t + p*256;                 // 2560
            int k = e/80, n = e%80;
            sXb[n*44 + k] = tf32u(Xb[(size_t)k*CSTR + n]);
        }
    }
    __syncthreads();

    float accY[10][4] = {};
    int Rr = w*16 + quad;

    for (int kc = 0; kc < 32; kc++){
        int cur = kc & 1;
        uint32_t* sQ = sQb + cur*(32*68);
        uint32_t* sX = sXb + cur*(80*44);
        uint32_t* nQ = sQb + (cur^1)*(32*68);
        uint32_t* nX = sXb + (cur^1)*(80*44);

        // prefetch next chunk (LDG latency hidden under adj phase)
        float4 pq[2];
        float  px[10];
        if (kc < 31){
            #pragma unroll
            for (int p = 0; p < 2; p++){
                int e = t + p*256;
                int c = e >> 4, m = e & 15;
                pq[p] = *(const float4*)&Qb[(size_t)((kc+1)*32 + c)*64 + m*4];
            }
            #pragma unroll
            for (int p = 0; p < 10; p++){
                int e = t + p*256;
                int k = e/80, n = e%80;
                px[p] = Xb[(size_t)((kc+1)*32 + k)*CSTR + n];
            }
        }

        // adj mma: this warp's 16 rows x 32 chunk-cols, K=64
        float accA[4][4] = {};
        #pragma unroll
        for (int k8 = 0; k8 < 8; k8++){
            int kk = k8*8;
            uint32_t a[4];
            a[0] = sP[(Rr  )*68 + kk + tig];
            a[1] = sP[(Rr+8)*68 + kk + tig];
            a[2] = sP[(Rr  )*68 + kk + tig + 4];
            a[3] = sP[(Rr+8)*68 + kk + tig + 4];
            #pragma unroll
            for (int nj = 0; nj < 4; nj++){
                int n = nj*8 + quad;
                uint32_t bq[2];
                bq[0] = sQ[n*68 + kk + tig];
                bq[1] = sQ[n*68 + kk + tig + 4];
                mma8(accA[nj], a, bq);
            }
        }

        // store prefetched next chunk (other buffer; current readers unaffected)
        if (kc < 31){
            #pragma unroll
            for (int p = 0; p < 2; p++){
                int e = t + p*256;
                int c = e >> 4, m = e & 15;
                uint4 u;
                u.x = tf32u(pq[p].x); u.y = tf32u(pq[p].y);
                u.z = tf32u(pq[p].z); u.w = tf32u(pq[p].w);
                *(uint4*)&nQ[c*68 + m*4] = u;
            }
            #pragma unroll
            for (int p = 0; p < 10; p++){
                int e = t + p*256;
                int k = e/80, n = e%80;
                nX[n*44 + k] = tf32u(px[p]);
            }
        }

        // relu + tf32 + in-register transpose, then spmm for this warp's rows
        #pragma unroll
        for (int nj = 0; nj < 4; nj++){
            uint32_t cu[4], aT[4];
            cu[0] = tf32u(fmaxf(accA[nj][0], 0.f));
            cu[1] = tf32u(fmaxf(accA[nj][1], 0.f));
            cu[2] = tf32u(fmaxf(accA[nj][2], 0.f));
            cu[3] = tf32u(fmaxf(accA[nj][3], 0.f));
            cfrag_to_afrag(cu, aT, quad, tig);
            int kk = nj*8;
            #pragma unroll
            for (int nb = 0; nb < 10; nb++){
                int n = nb*8 + quad;
                uint32_t bf[2];
                bf[0] = sX[n*44 + kk + tig];
                bf[1] = sX[n*44 + kk + tig + 4];
                mma8(accY[nb], aT, bf);
            }
        }
        __syncthreads();   // all reads of cur done; next buffers fully staged
    }

    // rowsum from ones-col 79 (nb=9, col 79 = 2*3+1 on tig==3): warp-local shfl
    const unsigned full = 0xffffffffu;
    float rs0 = __shfl_sync(full, accY[9][1], quad*4 + 3) + 1.f;   // row quad
    float rs1 = __shfl_sync(full, accY[9][3], quad*4 + 3) + 1.f;   // row quad+8
    float inv0 = 1.f/rs0, inv1 = 1.f/rs1;

    int row_a = row0 + Rr;
    int row_b = row_a + 8;
    const float* xa = Xb + (size_t)row_a*CSTR;
    const float* xb = Xb + (size_t)row_b*CSTR;
    float* ya = Y + ((size_t)b*Nn + row_a)*CSTR;
    float* yb = Y + ((size_t)b*Nn + row_b)*CSTR;
    #pragma unroll
    for (int nb = 0; nb < 10; nb++){
        int col = nb*8 + 2*tig;
        float2 va = *(const float2*)&xa[col];
        float2 vb = *(const float2*)&xb[col];
        float2 oa, ob;
        oa.x = (accY[nb][0] + va.x)*inv0;
        oa.y = (accY[nb][1] + va.y)*inv0;
        ob.x = (accY[nb][2] + vb.x)*inv1;
        ob.y = (accY[nb][3] + vb.y)*inv1;
        *(float2*)&ya[col] = oa;
        *(float2*)&yb[col] = ob;
    }
}

// ---------------- K5: gate node-GEMM -> z,r; builds cand (col79=1); inline bias ----
__global__ __launch_bounds__(128) void k_gate(const float* __restrict__ x,
                                              const float* __restrict__ state,
                                              const float* __restrict__ bg_pool,
                                              const float* __restrict__ ne2)
{
    extern __shared__ float sm[];
    float* sW0 = sm;
    float* sW1 = sm + COG;
    float* sX  = sm + 2*COG;
    float* sAX = sm + 2*COG + 2112;
    int n = blockIdx.x, t = threadIdx.x;
    int bg = t >> 5, og = t & 31;

    {
        float4* d0 = (float4*)sW0; const float4* s0 = (const float4*)(g_Wg0 + (size_t)n*COG);
        float4* d1 = (float4*)sW1; const float4* s1 = (const float4*)(g_Wg1 + (size_t)n*COG);
        for (int e = t; e < COG/4; e += 128){ d0[e] = s0[e]; d1[e] = s1[e]; }
    }
    for (int e = t; e < 32*66; e += 128){
        int bi = e/66, i = e%66;
        sX [e] = g_ins[((size_t)bi*Nn + n)*CSTR + i];
        sAX[e] = g_ax [((size_t)bi*Nn + n)*CSTR + i];
    }
    float4 bias = make_float4(0.f, 0.f, 0.f, 0.f);
    {
        #pragma unroll
        for (int d = 0; d < EDd; d++){
            float e = ne2[n*EDd + d];
            float4 bp = *(const float4*)&bg_pool[d*OGg + og*4];
            bias.x += e*bp.x; bias.y += e*bp.y; bias.z += e*bp.z; bias.w += e*bp.w;
        }
    }
    __syncthreads();

    float4 acc[8] = {};
    #pragma unroll 2
    for (int i = 0; i < 66; i++){
        float4 w0 = ((const float4*)sW0)[i*32 + og];
        float4 w1 = ((const float4*)sW1)[i*32 + og];
        #pragma unroll
        for (int bb = 0; bb < 8; bb++){
            int bi = bg*8 + bb;
            float xv = sX[bi*66 + i], av = sAX[bi*66 + i];
            acc[bb].x += xv*w0.x + av*w1.x;
            acc[bb].y += xv*w0.y + av*w1.y;
            acc[bb].z += xv*w0.z + av*w1.z;
            acc[bb].w += xv*w0.w + av*w1.w;
        }
    }
    int o0 = og*4;
    #pragma unroll
    for (int bb = 0; bb < 8; bb++){
        int bi = bg*8 + bb;
        size_t bn = (size_t)bi*Nn + n;
        float vals[4] = { acc[bb].x + bias.x, acc[bb].y + bias.y,
                          acc[bb].z + bias.z, acc[bb].w + bias.w };
        #pragma unroll
        for (int c = 0; c < 4; c++){
            float zz = sigm(vals[c]);
            int o = o0 + c;
            if (o < 64) g_cand[bn*CSTR + 2 + o] = zz * state[bn*64 + o];
            else        g_r  [bn*64 + (o - 64)] = zz;
        }
    }
    if (og == 0){
        #pragma unroll
        for (int bb = 0; bb < 8; bb++){
            size_t bn = (size_t)(bg*8 + bb)*Nn + n;
            g_cand[bn*CSTR + 0] = x[bn*2 + 0];
            g_cand[bn*CSTR + 1] = x[bn*2 + 1];
            #pragma unroll
            for (int c = 66; c < 80; c++) g_cand[bn*CSTR + c] = (c == 79) ? 1.f : 0.f;
        }
    }
}

// ---------------- K8: upd node-GEMM -> hc; final out; inline bias ----------------
__global__ __launch_bounds__(128) void k_upd(const float* __restrict__ state,
                                             float* __restrict__ out,
                                             const float* __restrict__ bu_pool,
                                             const float* __restrict__ ne2)
{
    extern __shared__ float sm[];
    float* sW0 = sm;
    float* sW1 = sm + COU;
    float* sX  = sm + 2*COU;
    float* sAX = sm + 2*COU + 2112;
    int n = blockIdx.x, t = threadIdx.x;
    int bg = t >> 5, og = t & 31;

    {
        float4* d0 = (float4*)sW0; const float4* s0 = (const float4*)(g_Wu0 + (size_t)n*COU);
        float4* d1 = (float4*)sW1; const float4* s1 = (const float4*)(g_Wu1 + (size_t)n*COU);
        for (int e = t; e < COU/4; e += 128){ d0[e] = s0[e]; d1[e] = s1[e]; }
    }
    for (int e = t; e < 32*66; e += 128){
        int bi = e/66, i = e%66;
        sX [e] = g_cand[((size_t)bi*Nn + n)*CSTR + i];
        sAX[e] = g_axc [((size_t)bi*Nn + n)*CSTR + i];
    }
    float2 bias = make_float2(0.f, 0.f);
    {
        #pragma unroll
        for (int d = 0; d < EDd; d++){
            float e = ne2[n*EDd + d];
            float2 bp = *(const float2*)&bu_pool[d*OUu + og*2];
            bias.x += e*bp.x; bias.y += e*bp.y;
        }
    }
    __syncthreads();

    float2 acc[8] = {};
    #pragma unroll 2
    for (int i = 0; i < 66; i++){
        float2 w0 = ((const float2*)sW0)[i*32 + og];
        float2 w1 = ((const float2*)sW1)[i*32 + og];
        #pragma unroll
        for (int bb = 0; bb < 8; bb++){
            int bi = bg*8 + bb;
            float xv = sX[bi*66 + i], av = sAX[bi*66 + i];
            acc[bb].x += xv*w0.x + av*w1.x;
            acc[bb].y += xv*w0.y + av*w1.y;
        }
    }
    #pragma unroll
    for (int bb = 0; bb < 8; bb++){
        int bi = bg*8 + bb;
        size_t bn = (size_t)bi*Nn + n;
        #pragma unroll
        for (int c = 0; c < 2; c++){
            int o = og*2 + c;
            float hc = tanhf((c ? acc[bb].y + bias.y : acc[bb].x + bias.x));
            float rr = g_r[bn*64 + o];
            float sv = state[bn*64 + o];
            out[bn*64 + o] = rr*sv + (1.f - rr)*hc;
        }
    }
}

// ---------------- launcher ----------------
extern "C" void kernel_launch(void* const* d_in, const int* in_sizes, int n_in,
                              void* d_out, int out_size)
{
    const float* x      = (const float*)d_in[0];
    const float* state  = (const float*)d_in[1];
    const float* ne0    = (const float*)d_in[2];
    const float* ne1    = (const float*)d_in[3];
    const float* ne2    = (const float*)d_in[4];
    const float* f1w1   = (const float*)d_in[5];
    const float* f1b1   = (const float*)d_in[6];
    const float* f1w2   = (const float*)d_in[7];
    const float* f1b2   = (const float*)d_in[8];
    const float* f1w3   = (const float*)d_in[9];
    const float* f1b3   = (const float*)d_in[10];
    const float* f2w1   = (const float*)d_in[11];
    const float* f2b1   = (const float*)d_in[12];
    const float* f2w2   = (const float*)d_in[13];
    const float* f2b2   = (const float*)d_in[14];
    const float* f2w3   = (const float*)d_in[15];
    const float* f2b3   = (const float*)d_in[16];
    const float* gate_w = (const float*)d_in[17];
    const float* gate_b = (const float*)d_in[18];
    const float* upd_w  = (const float*)d_in[19];
    const float* upd_b  = (const float*)d_in[20];
    float* out = (float*)d_out;

    cudaFuncSetAttribute(k_fused<false>, cudaFuncAttributeMaxDynamicSharedMemorySize, FUSED_SMEM);
    cudaFuncSetAttribute(k_fused<true>,  cudaFuncAttributeMaxDynamicSharedMemorySize, FUSED_SMEM);
    cudaFuncSetAttribute(k_gate, cudaFuncAttributeMaxDynamicSharedMemorySize, (2*COG + 2*2112)*4);
    cudaFuncSetAttribute(k_upd,  cudaFuncAttributeMaxDynamicSharedMemorySize, (2*COU + 2*2112)*4);

    // Launch #4 (the one ncu captures) = k_fused<false>.
    k_prep<<<256, 128>>>(x, state, ne0, ne1,
                         f1w1, f1b1, f1w2, f1b2, f1w3, f1b3,
                         f2w1, f2b1, f2w2, f2b2, f2w3, f2b3);
    k_wmix<COG, true ><<<dim3(COG/128, Nn/64), 128>>>(gate_w, ne2);
    k_wmix<COU, false><<<dim3(COU/128, Nn/64), 128>>>(upd_w,  ne2);
    k_fused<false><<<dim3(8, Bb), 256, FUSED_SMEM>>>();
    k_gate<<<Nn, 128, (2*COG + 2*2112)*4>>>(x, state, gate_b, ne2);
    k_fused<true><<<dim3(8, Bb), 256, FUSED_SMEM>>>();
    k_upd<<<Nn, 128, (2*COU + 2*2112)*4>>>(state, out, upd_b, ne2);
}

// round 17
// speedup vs baseline: 1.1177x; 1.0054x over previous
#include <cuda_runtime.h>
#include <cstdint>

#define Bb 32
#define Nn 1024
#define TDd 32
#define CINc 66
#define CSTR 80
#define EDd 10
#define OGg 128
#define OUu 64
#define COG (CINc*OGg)   // 8448
#define COU (CINc*OUu)   // 4224

typedef unsigned long long ull;

// ---------------- scratch ----------------
__device__ float g_ins  [Bb*Nn*CSTR];   // raw (scalar paths + epilogue add)
__device__ float g_insr [Bb*Nn*CSTR];   // tf32-rounded (mma path)
__device__ float g_p    [Bb*Nn*64];     // [nv1 | -nv2], tf32-rounded
__device__ float g_q    [Bb*Nn*64];     // [nv2 |  nv1], tf32-rounded
__device__ float g_ax   [Bb*Nn*CSTR];
__device__ float g_cand [Bb*Nn*CSTR];   // raw
__device__ float g_candr[Bb*Nn*CSTR];   // tf32-rounded
__device__ float g_axc  [Bb*Nn*CSTR];
__device__ float g_Wg0  [Nn*COG];
__device__ float g_Wg1  [Nn*COG];
__device__ float g_Wu0  [Nn*COU];
__device__ float g_Wu1  [Nn*COU];
__device__ float g_r    [Bb*Nn*OUu];

__device__ __forceinline__ float sigm(float v){ return 1.f/(1.f+__expf(-v)); }

// ---- tf32 mma.sync helpers (base-PTX only) ----
__device__ __forceinline__ uint32_t tf32u(float v){
    uint32_t o; asm("cvt.rna.tf32.f32 %0, %1;" : "=r"(o) : "f"(v)); return o;
}
__device__ __forceinline__ float tf32r(float v){
    return __uint_as_float(tf32u(v));
}
__device__ __forceinline__ void mma8(float* c, const uint32_t* a, const uint32_t* b){
    asm volatile("mma.sync.aligned.m16n8k8.row.col.f32.tf32.tf32.f32 "
        "{%0,%1,%2,%3}, {%4,%5,%6,%7}, {%8,%9}, {%0,%1,%2,%3};"
        : "+f"(c[0]), "+f"(c[1]), "+f"(c[2]), "+f"(c[3])
        : "r"(a[0]), "r"(a[1]), "r"(a[2]), "r"(a[3]), "r"(b[0]), "r"(b[1]));
}

// cp.async (LDGSTS; base PTX sm_80+)
__device__ __forceinline__ void cpa16(uint32_t dst, const void* src){
    asm volatile("cp.async.cg.shared.global [%0], [%1], 16;"
        :: "r"(dst), "l"(__cvta_generic_to_global(src)) : "memory");
}
__device__ __forceinline__ void cpa4(uint32_t dst, const void* src){
    asm volatile("cp.async.ca.shared.global [%0], [%1], 4;"
        :: "r"(dst), "l"(__cvta_generic_to_global(src)) : "memory");
}
#define CP_COMMIT() asm volatile("cp.async.commit_group;" ::: "memory")
#define CP_WAIT0()  asm volatile("cp.async.wait_group 0;" ::: "memory")

// C-fragment (16x8, relu'd tf32 uints) -> A-fragment (m16k8) via warp shuffles.
__device__ __forceinline__ void cfrag_to_afrag(const uint32_t cu[4], uint32_t aT[4],
                                               int quad, int tig){
    const unsigned full = 0xffffffffu;
    int s0 = quad*4 + (tig>>1);
    int s1 = s0 + 2;
    uint32_t x0 = __shfl_sync(full, cu[0], s0);
    uint32_t x1 = __shfl_sync(full, cu[1], s0);
    uint32_t x2 = __shfl_sync(full, cu[2], s0);
    uint32_t x3 = __shfl_sync(full, cu[3], s0);
    uint32_t y0 = __shfl_sync(full, cu[0], s1);
    uint32_t y1 = __shfl_sync(full, cu[1], s1);
    uint32_t y2 = __shfl_sync(full, cu[2], s1);
    uint32_t y3 = __shfl_sync(full, cu[3], s1);
    bool odd = (tig & 1) != 0;
    aT[0] = odd ? x1 : x0;
    aT[1] = odd ? x3 : x2;
    aT[2] = odd ? y1 : y0;
    aT[3] = odd ? y3 : y2;
}

// ---------------- K1: build ins/insr (col79=1), tiny MLPs -> p,q (rounded) ----
__global__ __launch_bounds__(128) void k_prep(
    const float* __restrict__ x, const float* __restrict__ st,
    const float* __restrict__ ne0, const float* __restrict__ ne1,
    const float* __restrict__ w11, const float* __restrict__ b11,
    const float* __restrict__ w12, const float* __restrict__ b12,
    const float* __restrict__ w13, const float* __restrict__ b13,
    const float* __restrict__ w21, const float* __restrict__ b21,
    const float* __restrict__ w22, const float* __restrict__ b22,
    const float* __restrict__ w23, const float* __restrict__ b23)
{
    __shared__ float sw11[1056], sw21[1056];
    __shared__ float sb11[16], sb21[16];
    __shared__ float sw12[32], sw22[32], sb12[2], sb22[2];
    __shared__ float sw13[64], sw23[64], sb13[32], sb23[32];
    __shared__ float sv[128*67];

    int t = threadIdx.x;
    for (int i = t; i < 1056; i += 128){ sw11[i] = w11[i]; sw21[i] = w21[i]; }
    if (t < 16){ sb11[t] = b11[t]; sb21[t] = b21[t]; }
    if (t < 32){
        sw12[t] = w12[t]; sw22[t] = w22[t];
        sw13[t] = w13[t]; sw23[t] = w23[t];
        sw13[32+t] = w13[32+t]; sw23[32+t] = w23[32+t];
        sb13[t] = b13[t]; sb23[t] = b23[t];
    }
    if (t < 2){ sb12[t] = b12[t]; sb22[t] = b22[t]; }

    int idx0 = blockIdx.x*128;
    for (int e = t; e < 256; e += 128){
        int r = e >> 1, c = e & 1;
        float v = x[idx0*2 + e];
        sv[r*67 + c] = v;
        g_ins [(size_t)(idx0+r)*CSTR + c] = v;
        g_insr[(size_t)(idx0+r)*CSTR + c] = tf32r(v);
    }
    for (int e = t; e < 128*64; e += 128){
        int r = e >> 6, c = e & 63;
        float v = st[(size_t)idx0*64 + e];
        sv[r*67 + 2 + c] = v;
        g_ins [(size_t)(idx0+r)*CSTR + 2 + c] = v;
        g_insr[(size_t)(idx0+r)*CSTR + 2 + c] = tf32r(v);
    }
    for (int e = t; e < 128*14; e += 128){
        int r = e/14, c = 66 + e%14;
        float v = (c == 79) ? 1.f : 0.f;
        g_ins [(size_t)(idx0+r)*CSTR + c] = v;
        g_insr[(size_t)(idx0+r)*CSTR + c] = v;
    }
    __syncthreads();

    int idx = idx0 + t;
    int b = idx >> 10;
    const float* vrow = &sv[t*67];

    {
        float h1[16];
        #pragma unroll
        for (int j = 0; j < 16; j++){
            float a = sb11[j];
            for (int i = 0; i < 66; i++) a += vrow[i]*sw11[i*16+j];
            h1[j] = sigm(a);
        }
        float a0 = sb12[0], a1 = sb12[1];
        #pragma unroll
        for (int j = 0; j < 16; j++){ a0 += h1[j]*sw12[j*2]; a1 += h1[j]*sw12[j*2+1]; }
        float h2a = sigm(a0), h2b = sigm(a1);
        #pragma unroll
        for (int o = 0; o < 32; o++){
            float f = sb13[o] + h2a*sw13[o] + h2b*sw13[32+o];
            float nv = tf32r(tanhf(ne0[b*TDd + o]*f));
            g_p[(size_t)idx*64 + o] = nv;
            g_q[(size_t)idx*64 + 32 + o] = nv;
        }
    }
    {
        float h1[16];
        #pragma unroll
        for (int j = 0; j < 16; j++){
            float a = sb21[j];
            for (int i = 0; i < 66; i++) a += vrow[i]*sw21[i*16+j];
            h1[j] = sigm(a);
        }
        float a0 = sb22[0], a1 = sb22[1];
        #pragma unroll
        for (int j = 0; j < 16; j++){ a0 += h1[j]*sw22[j*2]; a1 += h1[j]*sw22[j*2+1]; }
        float h2a = sigm(a0), h2b = sigm(a1);
        #pragma unroll
        for (int o = 0; o < 32; o++){
            float f = sb23[o] + h2a*sw23[o] + h2b*sw23[32+o];
            float nv = tf32r(tanhf(ne1[b*TDd + o]*f));
            g_p[(size_t)idx*64 + 32 + o] = -nv;
            g_q[(size_t)idx*64 + o] = nv;
        }
    }
}

// ---------------- K2: effective per-node weights ----------------
template<int CO, bool GATE>
__global__ __launch_bounds__(128) void k_wmix(const float* __restrict__ pool,
                                              const float* __restrict__ ne2)
{
    __shared__ float sne[64*EDd];
    int t = threadIdx.x;
    int row0 = blockIdx.y*64;
    for (int i = t; i < 64*EDd; i += 128) sne[i] = ne2[row0*EDd + i];
    __syncthreads();

    int col = blockIdx.x*128 + t;
    float ga[EDd], gb[EDd];
    #pragma unroll
    for (int d = 0; d < EDd; d++){
        ga[d] = pool[(size_t)(d*4+0)*CO + col] + pool[(size_t)(d*4+2)*CO + col];
        gb[d] = pool[(size_t)(d*4+1)*CO + col] + pool[(size_t)(d*4+3)*CO + col];
    }
    float* o0 = GATE ? g_Wg0 : g_Wu0;
    float* o1 = GATE ? g_Wg1 : g_Wu1;
    for (int r = 0; r < 64; r++){
        float a0 = 0.f, a1 = 0.f;
        #pragma unroll
        for (int d = 0; d < EDd; d++){ float e = sne[r*EDd+d]; a0 += e*ga[d]; a1 += e*gb[d]; }
        o0[(size_t)(row0+r)*CO + col] = a0;
        o1[(size_t)(row0+r)*CO + col] = a1;
    }
}

// ---------------- K3: FUSED  Y = (relu(P·Q^T) @ X + X)/rowsum ----------------
// 256 thr (8 warps), 128-row tile, grid (8, Bb), 2 CTAs/SM.
// P fragments live in registers for the whole kernel (no sP smem, no reloads).
// Inputs pre-rounded to tf32 -> staging is pure cp.async, zero in-loop cvt.
// One sync per chunk; rowsum via warp shfl from ones-col 79.
// smem words: sQ[2][32*68]=4352 @0 | sX[2][80*44]=7040 @4352 -> 11392 w = 45568 B
#define FUSED_SMEM (11392*4)
template<bool SECOND>
__global__ __launch_bounds__(256, 2) void k_fused(){
    extern __shared__ uint32_t fsm[];
    uint32_t* sQb = fsm;                       // [2][32*68]
    uint32_t* sXb = fsm + 4352;                // [2][80*44] (n-major, stride 44)
    const float* Xr = SECOND ? g_candr : g_insr;   // rounded (mma path)
    const float* Xw = SECOND ? g_cand  : g_ins;    // raw (epilogue add)
    float*       Y  = SECOND ? g_axc   : g_ax;
    int t = threadIdx.x, w = t >> 5, lane = t & 31;
    int quad = lane >> 2, tig = lane & 3;
    int b = blockIdx.y;
    int row0 = blockIdx.x*128;
    const uint32_t* Pb = (const uint32_t*)(g_p + (size_t)b*Nn*64);
    const float*    Qb = g_q + (size_t)b*Nn*64;
    const float*    Xb = Xr + (size_t)b*Nn*CSTR;
    int Rr = w*16 + quad;

    // P fragments once into registers (g_p pre-rounded)
    uint32_t aP[8][4];
    #pragma unroll
    for (int k8 = 0; k8 < 8; k8++){
        int kk = k8*8;
        aP[k8][0] = Pb[(size_t)(row0+Rr  )*64 + kk + tig];
        aP[k8][1] = Pb[(size_t)(row0+Rr+8)*64 + kk + tig];
        aP[k8][2] = Pb[(size_t)(row0+Rr  )*64 + kk + tig + 4];
        aP[k8][3] = Pb[(size_t)(row0+Rr+8)*64 + kk + tig + 4];
    }

    // stage chunk 0 via cp.async
    {
        #pragma unroll
        for (int p = 0; p < 2; p++){
            int e = t + p*256;                 // 512 x 16B = 32x64
            int c = e >> 4, m = e & 15;
            cpa16((uint32_t)__cvta_generic_to_shared(&sQb[c*68 + m*4]),
                  &Qb[(size_t)c*64 + m*4]);
        }
        #pragma unroll
        for (int p = 0; p < 10; p++){
            int e = t + p*256;                 // 2560 x 4B
            int k = e/80, n = e%80;
            cpa4((uint32_t)__cvta_generic_to_shared(&sXb[n*44 + k]),
                 &Xb[(size_t)k*CSTR + n]);
        }
        CP_COMMIT();
        CP_WAIT0();
    }
    __syncthreads();

    float accY[10][4] = {};

    for (int kc = 0; kc < 32; kc++){
        int cur = kc & 1;
        uint32_t* sQ = sQb + cur*(32*68);
        uint32_t* sX = sXb + cur*(80*44);
        uint32_t* nQ = sQb + (cur^1)*(32*68);
        uint32_t* nX = sXb + (cur^1)*(80*44);

        // async-stage next chunk (overlaps with compute below)
        if (kc < 31){
            #pragma unroll
            for (int p = 0; p < 2; p++){
                int e = t + p*256;
                int c = e >> 4, m = e & 15;
                cpa16((uint32_t)__cvta_generic_to_shared(&nQ[c*68 + m*4]),
                      &Qb[(size_t)((kc+1)*32 + c)*64 + m*4]);
            }
            #pragma unroll
            for (int p = 0; p < 10; p++){
                int e = t + p*256;
                int k = e/80, n = e%80;
                cpa4((uint32_t)__cvta_generic_to_shared(&nX[n*44 + k]),
                     &Xb[(size_t)((kc+1)*32 + k)*CSTR + n]);
            }
            CP_COMMIT();
        }

        // adj mma: this warp's 16 rows x 32 chunk-cols, K=64 (A from registers)
        float accA[4][4] = {};
        #pragma unroll
        for (int k8 = 0; k8 < 8; k8++){
            int kk = k8*8;
            #pragma unroll
            for (int nj = 0; nj < 4; nj++){
                int n = nj*8 + quad;
                uint32_t bq[2];
                bq[0] = sQ[n*68 + kk + tig];
                bq[1] = sQ[n*68 + kk + tig + 4];
                mma8(accA[nj], aP[k8], bq);
            }
        }

        // relu + tf32 + in-register transpose, then spmm for this warp's rows
        #pragma unroll
        for (int nj = 0; nj < 4; nj++){
            uint32_t cu[4], aT[4];
            cu[0] = tf32u(fmaxf(accA[nj][0], 0.f));
            cu[1] = tf32u(fmaxf(accA[nj][1], 0.f));
            cu[2] = tf32u(fmaxf(accA[nj][2], 0.f));
            cu[3] = tf32u(fmaxf(accA[nj][3], 0.f));
            cfrag_to_afrag(cu, aT, quad, tig);
            int kk = nj*8;
            #pragma unroll
            for (int nb = 0; nb < 10; nb++){
                int n = nb*8 + quad;
                uint32_t bf[2];
                bf[0] = sX[n*44 + kk + tig];
                bf[1] = sX[n*44 + kk + tig + 4];
                mma8(accY[nb], aT, bf);
            }
        }
        if (kc < 31) CP_WAIT0();
        __syncthreads();
    }

    // rowsum from ones-col 79 (nb=9, c1/c3 on tig==3): warp-local shfl
    const unsigned full = 0xffffffffu;
    float rs0 = __shfl_sync(full, accY[9][1], quad*4 + 3) + 1.f;
    float rs1 = __shfl_sync(full, accY[9][3], quad*4 + 3) + 1.f;
    float inv0 = 1.f/rs0, inv1 = 1.f/rs1;

    int row_a = row0 + Rr;
    int row_b = row_a + 8;
    const float* XwB = Xw + (size_t)b*Nn*CSTR;
    const float* xa = XwB + (size_t)row_a*CSTR;
    const float* xb = XwB + (size_t)row_b*CSTR;
    float* ya = Y + ((size_t)b*Nn + row_a)*CSTR;
    float* yb = Y + ((size_t)b*Nn + row_b)*CSTR;
    #pragma unroll
    for (int nb = 0; nb < 10; nb++){
        int col = nb*8 + 2*tig;
        float2 va = *(const float2*)&xa[col];
        float2 vb = *(const float2*)&xb[col];
        float2 oa, ob;
        oa.x = (accY[nb][0] + va.x)*inv0;
        oa.y = (accY[nb][1] + va.y)*inv0;
        ob.x = (accY[nb][2] + vb.x)*inv1;
        ob.y = (accY[nb][3] + vb.y)*inv1;
        *(float2*)&ya[col] = oa;
        *(float2*)&yb[col] = ob;
    }
}

// ---------------- K5: gate node-GEMM -> z,r; builds cand/candr; inline bias ----
__global__ __launch_bounds__(128) void k_gate(const float* __restrict__ x,
                                              const float* __restrict__ state,
                                              const float* __restrict__ bg_pool,
                                              const float* __restrict__ ne2)
{
    extern __shared__ float sm[];
    float* sW0 = sm;
    float* sW1 = sm + COG;
    float* sX  = sm + 2*COG;
    float* sAX = sm + 2*COG + 2112;
    int n = blockIdx.x, t = threadIdx.x;
    int bg = t >> 5, og = t & 31;

    {
        float4* d0 = (float4*)sW0; const float4* s0 = (const float4*)(g_Wg0 + (size_t)n*COG);
        float4* d1 = (float4*)sW1; const float4* s1 = (const float4*)(g_Wg1 + (size_t)n*COG);
        for (int e = t; e < COG/4; e += 128){ d0[e] = s0[e]; d1[e] = s1[e]; }
    }
    for (int e = t; e < 32*66; e += 128){
        int bi = e/66, i = e%66;
        sX [e] = g_ins[((size_t)bi*Nn + n)*CSTR + i];
        sAX[e] = g_ax [((size_t)bi*Nn + n)*CSTR + i];
    }
    float4 bias = make_float4(0.f, 0.f, 0.f, 0.f);
    {
        #pragma unroll
        for (int d = 0; d < EDd; d++){
            float e = ne2[n*EDd + d];
            float4 bp = *(const float4*)&bg_pool[d*OGg + og*4];
            bias.x += e*bp.x; bias.y += e*bp.y; bias.z += e*bp.z; bias.w += e*bp.w;
        }
    }
    __syncthreads();

    float4 acc[8] = {};
    #pragma unroll 2
    for (int i = 0; i < 66; i++){
        float4 w0 = ((const float4*)sW0)[i*32 + og];
        float4 w1 = ((const float4*)sW1)[i*32 + og];
        #pragma unroll
        for (int bb = 0; bb < 8; bb++){
            int bi = bg*8 + bb;
            float xv = sX[bi*66 + i], av = sAX[bi*66 + i];
            acc[bb].x += xv*w0.x + av*w1.x;
            acc[bb].y += xv*w0.y + av*w1.y;
            acc[bb].z += xv*w0.z + av*w1.z;
            acc[bb].w += xv*w0.w + av*w1.w;
        }
    }
    int o0 = og*4;
    #pragma unroll
    for (int bb = 0; bb < 8; bb++){
        int bi = bg*8 + bb;
        size_t bn = (size_t)bi*Nn + n;
        float vals[4] = { acc[bb].x + bias.x, acc[bb].y + bias.y,
                          acc[bb].z + bias.z, acc[bb].w + bias.w };
        #pragma unroll
        for (int c = 0; c < 4; c++){
            float zz = sigm(vals[c]);
            int o = o0 + c;
            if (o < 64){
                float cv = zz * state[bn*64 + o];
                g_cand [bn*CSTR + 2 + o] = cv;
                g_candr[bn*CSTR + 2 + o] = tf32r(cv);
            } else {
                g_r[bn*64 + (o - 64)] = zz;
            }
        }
    }
    if (og == 0){
        #pragma unroll
        for (int bb = 0; bb < 8; bb++){
            size_t bn = (size_t)(bg*8 + bb)*Nn + n;
            float x0 = x[bn*2 + 0], x1 = x[bn*2 + 1];
            g_cand [bn*CSTR + 0] = x0;  g_candr[bn*CSTR + 0] = tf32r(x0);
            g_cand [bn*CSTR + 1] = x1;  g_candr[bn*CSTR + 1] = tf32r(x1);
            #pragma unroll
            for (int c = 66; c < 80; c++){
                float v = (c == 79) ? 1.f : 0.f;
                g_cand [bn*CSTR + c] = v;
                g_candr[bn*CSTR + c] = v;
            }
        }
    }
}

// ---------------- K8: upd node-GEMM -> hc; final out; inline bias ----------------
__global__ __launch_bounds__(128) void k_upd(const float* __restrict__ state,
                                             float* __restrict__ out,
                                             const float* __restrict__ bu_pool,
                                             const float* __restrict__ ne2)
{
    extern __shared__ float sm[];
    float* sW0 = sm;
    float* sW1 = sm + COU;
    float* sX  = sm + 2*COU;
    float* sAX = sm + 2*COU + 2112;
    int n = blockIdx.x, t = threadIdx.x;
    int bg = t >> 5, og = t & 31;

    {
        float4* d0 = (float4*)sW0; const float4* s0 = (const float4*)(g_Wu0 + (size_t)n*COU);
        float4* d1 = (float4*)sW1; const float4* s1 = (const float4*)(g_Wu1 + (size_t)n*COU);
        for (int e = t; e < COU/4; e += 128){ d0[e] = s0[e]; d1[e] = s1[e]; }
    }
    for (int e = t; e < 32*66; e += 128){
        int bi = e/66, i = e%66;
        sX [e] = g_cand[((size_t)bi*Nn + n)*CSTR + i];
        sAX[e] = g_axc [((size_t)bi*Nn + n)*CSTR + i];
    }
    float2 bias = make_float2(0.f, 0.f);
    {
        #pragma unroll
        for (int d = 0; d < EDd; d++){
            float e = ne2[n*EDd + d];
            float2 bp = *(const float2*)&bu_pool[d*OUu + og*2];
            bias.x += e*bp.x; bias.y += e*bp.y;
        }
    }
    __syncthreads();

    float2 acc[8] = {};
    #pragma unroll 2
    for (int i = 0; i < 66; i++){
        float2 w0 = ((const float2*)sW0)[i*32 + og];
        float2 w1 = ((const float2*)sW1)[i*32 + og];
        #pragma unroll
        for (int bb = 0; bb < 8; bb++){
            int bi = bg*8 + bb;
            float xv = sX[bi*66 + i], av = sAX[bi*66 + i];
            acc[bb].x += xv*w0.x + av*w1.x;
            acc[bb].y += xv*w0.y + av*w1.y;
        }
    }
    #pragma unroll
    for (int bb = 0; bb < 8; bb++){
        int bi = bg*8 + bb;
        size_t bn = (size_t)bi*Nn + n;
        #pragma unroll
        for (int c = 0; c < 2; c++){
            int o = og*2 + c;
            float hc = tanhf((c ? acc[bb].y + bias.y : acc[bb].x + bias.x));
            float rr = g_r[bn*64 + o];
            float sv = state[bn*64 + o];
            out[bn*64 + o] = rr*sv + (1.f - rr)*hc;
        }
    }
}

// ---------------- launcher ----------------
extern "C" void kernel_launch(void* const* d_in, const int* in_sizes, int n_in,
                              void* d_out, int out_size)
{
    const float* x      = (const float*)d_in[0];
    const float* state  = (const float*)d_in[1];
    const float* ne0    = (const float*)d_in[2];
    const float* ne1    = (const float*)d_in[3];
    const float* ne2    = (const float*)d_in[4];
    const float* f1w1   = (const float*)d_in[5];
    const float* f1b1   = (const float*)d_in[6];
    const float* f1w2   = (const float*)d_in[7];
    const float* f1b2   = (const float*)d_in[8];
    const float* f1w3   = (const float*)d_in[9];
    const float* f1b3   = (const float*)d_in[10];
    const float* f2w1   = (const float*)d_in[11];
    const float* f2b1   = (const float*)d_in[12];
    const float* f2w2   = (const float*)d_in[13];
    const float* f2b2   = (const float*)d_in[14];
    const float* f2w3   = (const float*)d_in[15];
    const float* f2b3   = (const float*)d_in[16];
    const float* gate_w = (const float*)d_in[17];
    const float* gate_b = (const float*)d_in[18];
    const float* upd_w  = (const float*)d_in[19];
    const float* upd_b  = (const float*)d_in[20];
    float* out = (float*)d_out;

    cudaFuncSetAttribute(k_fused<false>, cudaFuncAttributeMaxDynamicSharedMemorySize, FUSED_SMEM);
    cudaFuncSetAttribute(k_fused<true>,  cudaFuncAttributeMaxDynamicSharedMemorySize, FUSED_SMEM);
    cudaFuncSetAttribute(k_gate, cudaFuncAttributeMaxDynamicSharedMemorySize, (2*COG + 2*2112)*4);
    cudaFuncSetAttribute(k_upd,  cudaFuncAttributeMaxDynamicSharedMemorySize, (2*COU + 2*2112)*4);

    // Launch #4 (the one ncu captures) = k_fused<false>.
    k_prep<<<256, 128>>>(x, state, ne0, ne1,
                         f1w1, f1b1, f1w2, f1b2, f1w3, f1b3,
                         f2w1, f2b1, f2w2, f2b2, f2w3, f2b3);
    k_wmix<COG, true ><<<dim3(COG/128, Nn/64), 128>>>(gate_w, ne2);
    k_wmix<COU, false><<<dim3(COU/128, Nn/64), 128>>>(upd_w,  ne2);
    k_fused<false><<<dim3(8, Bb), 256, FUSED_SMEM>>>();
    k_gate<<<Nn, 128, (2*COG + 2*2112)*4>>>(x, state, gate_b, ne2);
    k_fused<true><<<dim3(8, Bb), 256, FUSED_SMEM>>>();
    k_upd<<<Nn, 128, (2*COU + 2*2112)*4>>>(state, out, upd_b, ne2);
}